// round 13
// baseline (speedup 1.0000x reference)
#include <cuda_runtime.h>
#include <cuda_fp16.h>
#include <cstdint>

// Problem constants (fixed shapes)
#define Tt 2048
#define Bb 8
#define Dd 512
#define Ss 4
#define GHh 64

// ---------------- scratch (static device globals; no runtime alloc) ----------------
__device__ __half g_wencH[(size_t)Bb*Tt*Ss*Dd]; // wenc stored fp16, layout [t][b][s][d]
__device__ float g_hpart[(size_t)Bb*Tt*Ss*GHh];  // layout [t][b][s][h]
__device__ float g_errsq[Tt*Bb*Ss];              // sum_d (pred_prev - h)^2, [t][b][s]
__device__ float g_mu   [Tt*Ss];
__device__ float g_sig  [Tt*Ss];
__device__ float g_gall [3*Tt*Bb*Ss];            // [st][t][b][s]
__device__ float g_gmean[3*Tt*Ss];
__device__ float g_ge   [Tt*Bb*Ss];
__device__ float g_seb  [3*Ss*GHh];

// fp16 operands: A (h_seq) hi/lo split; weights hi only
__device__ __half g_Ahi[(size_t)Bb*Tt*Dd];
__device__ __half g_Alo[(size_t)Bb*Tt*Dd];
__device__ __half g_PW [Ss*Dd*Dd];               // pred_W^T  [s][n][k]
__device__ __half g_WW [Ss*Dd*Dd];               // write_W^T
__device__ __half g_GW [Ss*GHh*Dd];              // gate_W1[0:512]^T

// ======================= portable PTX helpers (sm_80-level) =======================
__device__ __forceinline__ uint32_t smem_u32(const void* p) {
    uint32_t a;
    asm("{ .reg .u64 t; cvta.to.shared.u64 t, %1; cvt.u32.u64 %0, t; }" : "=r"(a) : "l"(p));
    return a;
}
#define CP_ASYNC16(dst, src) \
    asm volatile("cp.async.cg.shared.global [%0], [%1], 16;" :: "r"(dst), "l"(src))
#define CP_ASYNC8(dst, src) \
    asm volatile("cp.async.ca.shared.global [%0], [%1], 8;" :: "r"(dst), "l"(src))
#define CP_COMMIT() asm volatile("cp.async.commit_group;" ::: "memory")
#define CP_WAIT(n)  asm volatile("cp.async.wait_group %0;" :: "n"(n) : "memory")

__device__ __forceinline__ void ldsm_x4(uint32_t* r, uint32_t addr) {
    asm volatile("ldmatrix.sync.aligned.m8n8.x4.shared.b16 {%0,%1,%2,%3}, [%4];"
        : "=r"(r[0]), "=r"(r[1]), "=r"(r[2]), "=r"(r[3]) : "r"(addr));
}
__device__ __forceinline__ void mma16816(float* d, const uint32_t* a, const uint32_t* b) {
    asm volatile("mma.sync.aligned.m16n8k16.row.col.f32.f16.f16.f32 "
        "{%0,%1,%2,%3}, {%4,%5,%6,%7}, {%8,%9}, {%0,%1,%2,%3};"
        : "+f"(d[0]), "+f"(d[1]), "+f"(d[2]), "+f"(d[3])
        : "r"(a[0]), "r"(a[1]), "r"(a[2]), "r"(a[3]), "r"(b[0]), "r"(b[1]));
}
__device__ __forceinline__ uint32_t sw128(uint32_t bo) { return bo ^ ((bo >> 3) & 0x70); }

// ======================= conversion pre-passes =======================
__global__ void convert_h_kernel(const float* __restrict__ h,
                                 __half* __restrict__ hi,
                                 __half* __restrict__ lo) {
    size_t i = (size_t)blockIdx.x * 256 + threadIdx.x;
    float v = h[i];
    __half a = __float2half(v);
    hi[i] = a;
    lo[i] = __float2half(v - __half2float(a));
    if (blockIdx.x < (Tt * Bb * Ss) / 256)
        g_errsq[blockIdx.x * 256 + threadIdx.x] = 0.f;
}

__global__ void transpose_both_kernel(const float* __restrict__ predW,
                                      const float* __restrict__ writeW,
                                      __half* __restrict__ dPW,
                                      __half* __restrict__ dWW) {
    __shared__ float tile[32][33];
    int s = blockIdx.z & 3;
    int which = blockIdx.z >> 2;
    const float* src = (which == 0) ? predW : writeW;
    __half* dst = (which == 0) ? dPW : dWW;
    int n0 = blockIdx.x * 32, k0 = blockIdx.y * 32;
    const float* sp = src + (size_t)s * Dd * Dd;
    for (int i = threadIdx.y; i < 32; i += 8)
        tile[i][threadIdx.x] = sp[(size_t)(k0 + i) * Dd + n0 + threadIdx.x];
    __syncthreads();
    size_t dbase = (size_t)s * Dd * 512;
    for (int i = threadIdx.y; i < 32; i += 8) {
        float v = tile[threadIdx.x][i];
        size_t off = dbase + (size_t)(n0 + i) * 512 + k0 + threadIdx.x;
        dst[off] = __float2half(v);
    }
}

__global__ void transpose_gw_kernel(const float* __restrict__ src,
                                    __half* __restrict__ dhi) {
    __shared__ float tile[32][33];
    int s = blockIdx.z;
    int n0 = blockIdx.x * 32, k0 = blockIdx.y * 32;
    const float* sp = src + (size_t)s * 521 * GHh;
    for (int i = threadIdx.y; i < 32; i += 8)
        tile[i][threadIdx.x] = sp[(size_t)(k0 + i) * GHh + n0 + threadIdx.x];
    __syncthreads();
    size_t dbase = (size_t)s * GHh * 512;
    for (int i = threadIdx.y; i < 32; i += 8) {
        float v = tile[threadIdx.x][i];
        size_t off = dbase + (size_t)(n0 + i) * 512 + k0 + threadIdx.x;
        dhi[off] = __float2half(v);
    }
}

// ====== BIG GEMM: BM=128, BN=128, 1-pass fp16, 16 warps (4m x 4n, 32x32 tiles) =========
// __launch_bounds__(512, 2): 2 CTAs/SM (64 KB smem each, <=63 regs) -> 8 warps/SMSP
__device__ __forceinline__ void load_chunk_big(int tid, uint32_t base,
    const __half* __restrict__ Ahi, const __half* __restrict__ Bhi, int k0) {
    constexpr int A_BYTES = 128 * 128;
#pragma unroll
    for (int it = 0; it < 4; it++) {               // 256 rows x 8 segs / 512 threads
        int idx = tid + it * 512;
        int seg = idx & 7, q = idx >> 3;
        const __half* src;
        uint32_t toff;
        int r;
        if (q < 128) { src = Ahi; toff = 0;       r = q; }
        else         { src = Bhi; toff = A_BYTES; r = q - 128; }
        uint32_t bo = r * 128 + seg * 16;
        uint32_t dst = base + toff + sw128(bo);
        const void* g = (const void*)(src + (size_t)r * 512 + k0 + seg * 8);
        CP_ASYNC16(dst, g);
    }
}

template<bool FUSE_ERR, bool OUT_HALF>
__global__ void __launch_bounds__(512, 2)
mma_gemm_big(const __half* __restrict__ Ahi, const __half* __restrict__ BhiBase,
             const float* __restrict__ biasBase, void* __restrict__ outBase,
             const float* __restrict__ hseq) {
    constexpr int NC = 8;
    constexpr int A_BYTES = 128 * 128;
    constexpr int B_BYTES = 128 * 128;
    constexpr int STAGE = A_BYTES + B_BYTES;       // 32768
    constexpr int NF = 4;                          // warp N = 32
    constexpr int MF = 2;                          // warp M = 32

    extern __shared__ char smem[];
    const uint32_t tiles = smem_u32(smem);

    const int s = blockIdx.z;
    const int nBlock = blockIdx.x * 128;
    const int mBlock = blockIdx.y * 128;
    const __half* Ahi_t = Ahi + (size_t)mBlock * 512;
    const __half* Bhi_t = BhiBase + ((size_t)s * 512 + nBlock) * 512;
    const float* bias = biasBase + s * 512 + nBlock;

    const int tid = threadIdx.x;
    const int lane = tid & 31, w = tid >> 5;
    const int wm = (w & 3) * 32;
    const int wn = (w >> 2) * 32;

    float acc[MF][NF][4];
#pragma unroll
    for (int mf = 0; mf < MF; mf++)
#pragma unroll
        for (int nf = 0; nf < NF; nf++)
#pragma unroll
            for (int i = 0; i < 4; i++) acc[mf][nf][i] = 0.f;

    const uint32_t aRow = (uint32_t)(wm + (lane & 15));
    const uint32_t aCol = (uint32_t)((lane >> 4) * 16);
    const uint32_t bRow = (uint32_t)(wn + ((lane >> 4) & 1) * 8 + (lane & 7));
    const uint32_t bCol = (uint32_t)(((lane >> 3) & 1) * 16);

    load_chunk_big(tid, tiles, Ahi_t, Bhi_t, 0);
    CP_COMMIT();

    for (int ck = 0; ck < NC; ck++) {
        const int nx = ck + 1;
        if (nx < NC) {
            load_chunk_big(tid, tiles + (nx & 1) * STAGE, Ahi_t, Bhi_t, nx * 64);
            CP_COMMIT();
            CP_WAIT(1);
        } else {
            CP_WAIT(0);
        }
        __syncthreads();

        const uint32_t aH = tiles + (ck & 1) * STAGE;
        const uint32_t bH = aH + A_BYTES;

#pragma unroll
        for (int k16 = 0; k16 < 4; k16++) {
            uint32_t fa[MF][4];
#pragma unroll
            for (int mf = 0; mf < MF; mf++) {
                uint32_t bo = (aRow + mf * 16) * 128 + (uint32_t)(k16 * 32) + aCol;
                ldsm_x4(fa[mf], aH + sw128(bo));
            }
            uint32_t fb[NF][2];
#pragma unroll
            for (int nf2 = 0; nf2 < NF / 2; nf2++) {
                uint32_t bo = (bRow + nf2 * 16) * 128 + (uint32_t)(k16 * 32) + bCol;
                uint32_t r[4];
                ldsm_x4(r, bH + sw128(bo));
                fb[2*nf2][0] = r[0]; fb[2*nf2][1] = r[1];
                fb[2*nf2+1][0] = r[2]; fb[2*nf2+1][1] = r[3];
            }
#pragma unroll
            for (int mf = 0; mf < MF; mf++)
#pragma unroll
                for (int nf = 0; nf < NF; nf++)
                    mma16816(acc[mf][nf], fa[mf], fb[nf]);
        }
        __syncthreads();
    }

#pragma unroll
    for (int mf = 0; mf < MF; mf++) {
#pragma unroll
        for (int rr = 0; rr < 2; rr++) {
            int m = mBlock + wm + mf * 16 + rr * 8 + (lane >> 2);  // m = b*T + t
            int t = m & (Tt - 1), b = m >> 11;
            if (FUSE_ERR) {
                float ssum = 0.f;
                if (t < Tt - 1) {
                    const float* hrow = hseq + ((size_t)(b * Tt + t + 1)) * Dd + nBlock;
#pragma unroll
                    for (int nf = 0; nf < NF; nf++) {
                        int col = wn + nf * 8 + (lane & 3) * 2;
                        float2 hv = *(const float2*)&hrow[col];
                        float dx = acc[mf][nf][2 * rr]     + bias[col]     - hv.x;
                        float dy = acc[mf][nf][2 * rr + 1] + bias[col + 1] - hv.y;
                        ssum += dx * dx + dy * dy;
                    }
                }
                ssum += __shfl_xor_sync(0xffffffffu, ssum, 1);
                ssum += __shfl_xor_sync(0xffffffffu, ssum, 2);
                if ((lane & 3) == 0 && t < Tt - 1)
                    atomicAdd(&g_errsq[(t + 1) * 32 + b * 4 + s], ssum);
            } else {
                size_t rowoff = ((size_t)(t * Bb + b) * Ss + s) * 512 + nBlock;
#pragma unroll
                for (int nf = 0; nf < NF; nf++) {
                    int col = wn + nf * 8 + (lane & 3) * 2;
                    float vx = acc[mf][nf][2 * rr]     + bias[col];
                    float vy = acc[mf][nf][2 * rr + 1] + bias[col + 1];
                    if (OUT_HALF) {
                        __half2 hv = __floats2half2_rn(vx, vy);
                        *(__half2*)((__half*)outBase + rowoff + col) = hv;
                    } else {
                        float2 v; v.x = vx; v.y = vy;
                        *(float2*)((float*)outBase + rowoff + col) = v;
                    }
                }
            }
        }
    }
}

// ============ gate GEMM: BM=128, BN=64, 2-pass, 16 warps, 2 CTAs/SM ============
__device__ __forceinline__ void load_chunk_gate(int tid, uint32_t base,
    const __half* __restrict__ Ahi, const __half* __restrict__ Alo,
    const __half* __restrict__ Bhi, int k0) {
    constexpr int A_BYTES = 128 * 128;
#pragma unroll
    for (int it = 0; it < 5; it++) {
        int idx = tid + it * 512;
        int seg = idx & 7, q = idx >> 3;
        const __half* src;
        uint32_t toff;
        int r;
        if (q < 128)      { src = Ahi; toff = 0;            r = q; }
        else if (q < 256) { src = Alo; toff = A_BYTES;      r = q - 128; }
        else              { src = Bhi; toff = 2 * A_BYTES;  r = q - 256; }
        uint32_t bo = r * 128 + seg * 16;
        uint32_t dst = base + toff + sw128(bo);
        const void* g = (const void*)(src + (size_t)r * 512 + k0 + seg * 8);
        CP_ASYNC16(dst, g);
    }
}

__global__ void __launch_bounds__(512, 2)
mma_gemm_gate(const __half* __restrict__ Ahi, const __half* __restrict__ Alo,
              const __half* __restrict__ BhiBase,
              const float* __restrict__ biasBase, float* __restrict__ outBase) {
    constexpr int NC = 8;
    constexpr int A_BYTES = 128 * 128;
    constexpr int B_BYTES = 64 * 128;
    constexpr int STAGE = 2 * A_BYTES + B_BYTES;   // 40960
    constexpr int NF = 2;

    extern __shared__ char smem[];
    const uint32_t tiles = smem_u32(smem);

    const int s = blockIdx.z;
    const int mBlock = blockIdx.y * 128;
    const __half* Ahi_t = Ahi + (size_t)mBlock * 512;
    const __half* Alo_t = Alo + (size_t)mBlock * 512;
    const __half* Bhi_t = BhiBase + (size_t)s * GHh * 512;
    const float* bias = biasBase + s * GHh;

    const int tid = threadIdx.x;
    const int lane = tid & 31, w = tid >> 5;
    const int wm = (w & 3) * 32;
    const int wn = (w >> 2) * 16;

    float acc[2][NF][4];
#pragma unroll
    for (int mf = 0; mf < 2; mf++)
#pragma unroll
        for (int nf = 0; nf < NF; nf++)
#pragma unroll
            for (int i = 0; i < 4; i++) acc[mf][nf][i] = 0.f;

    const uint32_t aRow = (uint32_t)(wm + (lane & 15));
    const uint32_t aCol = (uint32_t)((lane >> 4) * 16);
    const uint32_t bRow = (uint32_t)(wn + ((lane >> 4) & 1) * 8 + (lane & 7));
    const uint32_t bCol = (uint32_t)(((lane >> 3) & 1) * 16);

    load_chunk_gate(tid, tiles, Ahi_t, Alo_t, Bhi_t, 0);
    CP_COMMIT();

    for (int ck = 0; ck < NC; ck++) {
        const int nx = ck + 1;
        if (nx < NC) {
            load_chunk_gate(tid, tiles + (nx & 1) * STAGE, Ahi_t, Alo_t, Bhi_t, nx * 64);
            CP_COMMIT();
            CP_WAIT(1);
        } else {
            CP_WAIT(0);
        }
        __syncthreads();

        const uint32_t aH = tiles + (ck & 1) * STAGE;
        const uint32_t aL = aH + A_BYTES;
        const uint32_t bH = aH + 2 * A_BYTES;

#pragma unroll
        for (int k16 = 0; k16 < 4; k16++) {
            uint32_t fa_h[2][4], fa_l[2][4];
#pragma unroll
            for (int mf = 0; mf < 2; mf++) {
                uint32_t bo = (aRow + mf * 16) * 128 + (uint32_t)(k16 * 32) + aCol;
                ldsm_x4(fa_h[mf], aH + sw128(bo));
                ldsm_x4(fa_l[mf], aL + sw128(bo));
            }
            uint32_t fb[NF][2];
            {
                uint32_t bo = bRow * 128 + (uint32_t)(k16 * 32) + bCol;
                uint32_t r[4];
                ldsm_x4(r, bH + sw128(bo));
                fb[0][0] = r[0]; fb[0][1] = r[1];
                fb[1][0] = r[2]; fb[1][1] = r[3];
            }
#pragma unroll
            for (int mf = 0; mf < 2; mf++)
#pragma unroll
                for (int nf = 0; nf < NF; nf++) {
                    mma16816(acc[mf][nf], fa_h[mf], fb[nf]);
                    mma16816(acc[mf][nf], fa_l[mf], fb[nf]);
                }
        }
        __syncthreads();
    }

#pragma unroll
    for (int mf = 0; mf < 2; mf++) {
#pragma unroll
        for (int rr = 0; rr < 2; rr++) {
            int m = mBlock + wm + mf * 16 + rr * 8 + (lane >> 2);
            int t = m & (Tt - 1), b = m >> 11;
            float* orow = outBase + ((size_t)(t * Bb + b) * Ss + s) * GHh;
#pragma unroll
            for (int nf = 0; nf < NF; nf++) {
                int col = wn + nf * 8 + (lane & 3) * 2;
                float2 v;
                v.x = acc[mf][nf][2 * rr]     + bias[col];
                v.y = acc[mf][nf][2 * rr + 1] + bias[col + 1];
                *(float2*)&orow[col] = v;
            }
        }
    }
}

// ---------------- seb: state_embed @ gate_W1[513:521] ----------------
__global__ void seb_kernel(const float* __restrict__ gate_W1,
                           const float* __restrict__ state_embed) {
    int i = blockIdx.x * blockDim.x + threadIdx.x;
    if (i >= 3 * Ss * GHh) return;
    int h = i % GHh;
    int s = (i / GHh) % Ss;
    int st = i / (GHh * Ss);
    float acc = 0.f;
#pragma unroll
    for (int e = 0; e < 8; e++)
        acc += state_embed[st * 8 + e] * gate_W1[((size_t)s * 521 + 513 + e) * GHh + h];
    g_seb[i] = acc;
}

// ============ fused stats: em (par) -> mu chain (LDS) -> dev (par) -> sigma chain ======
__global__ void __launch_bounds__(1024, 1) stats_kernel() {
    extern __shared__ float dyn[];
    float* sem = dyn;
    float* smu = dyn + Tt * Ss;
    float* sdv = dyn + 2 * Tt * Ss;
    const int tid = threadIdx.x;

    for (int t = tid; t < Tt; t += 1024) {
        float s0 = 0.f, s1 = 0.f, s2 = 0.f, s3 = 0.f;
        if (t > 0) {
            const float4* p = (const float4*)&g_errsq[t * 32];
#pragma unroll
            for (int b = 0; b < Bb; b++) {
                float4 v = p[b];
                s0 += sqrtf(v.x + 1e-8f);
                s1 += sqrtf(v.y + 1e-8f);
                s2 += sqrtf(v.z + 1e-8f);
                s3 += sqrtf(v.w + 1e-8f);
            }
        }
        sem[t * 4 + 0] = s0 * 0.125f;
        sem[t * 4 + 1] = s1 * 0.125f;
        sem[t * 4 + 2] = s2 * 0.125f;
        sem[t * 4 + 3] = s3 * 0.125f;
    }
    __syncthreads();

    if (tid < Ss) {
        float mu = 0.f;
#pragma unroll 8
        for (int t = 0; t < Tt; t++) {
            smu[t * 4 + tid] = mu;
            g_mu[t * 4 + tid] = mu;
            float e = sem[t * 4 + tid];
            if (t > 0) mu = 0.99f * mu + 0.01f * e;
        }
    }
    __syncthreads();

    for (int t = tid; t < Tt; t += 1024) {
        float m0 = smu[t * 4 + 0], m1 = smu[t * 4 + 1];
        float m2 = smu[t * 4 + 2], m3 = smu[t * 4 + 3];
        float s0 = 0.f, s1 = 0.f, s2 = 0.f, s3 = 0.f;
        if (t > 0) {
            const float4* p = (const float4*)&g_errsq[t * 32];
#pragma unroll
            for (int b = 0; b < Bb; b++) {
                float4 v = p[b];
                s0 += fabsf(sqrtf(v.x + 1e-8f) - m0);
                s1 += fabsf(sqrtf(v.y + 1e-8f) - m1);
                s2 += fabsf(sqrtf(v.z + 1e-8f) - m2);
                s3 += fabsf(sqrtf(v.w + 1e-8f) - m3);
            }
        }
        sdv[t * 4 + 0] = s0 * 0.125f;
        sdv[t * 4 + 1] = s1 * 0.125f;
        sdv[t * 4 + 2] = s2 * 0.125f;
        sdv[t * 4 + 3] = s3 * 0.125f;
    }
    __syncthreads();

    if (tid < Ss) {
        float sg = 1.f;
#pragma unroll 8
        for (int t = 0; t < Tt; t++) {
            g_sig[t * 4 + tid] = sg;
            float d = sdv[t * 4 + tid];
            if (t > 0) sg = 0.99f * sg + 0.01f * d;
        }
    }
}

// ====== gate MLP over all 3 states, fused with gmean (block per t, warps loop b) ======
__global__ void __launch_bounds__(384, 1)
gall_kernel(const float* __restrict__ gate_W1,
            const float* __restrict__ gate_W2,
            const float* __restrict__ gate_b2) {
    int t = blockIdx.x;
    int w = threadIdx.x >> 5, lane = threadIdx.x & 31;
    int st = w >> 2, s = w & 3;

    float mu = g_mu[t * Ss + s];
    float sig = fmaxf(g_sig[t * Ss + s], 1e-3f);
    float w1z0 = gate_W1[((size_t)s * 521 + 512) * GHh + lane];
    float w1z1 = gate_W1[((size_t)s * 521 + 512) * GHh + lane + 32];
    float sb0 = g_seb[(st * Ss + s) * GHh + lane];
    float sb1 = g_seb[(st * Ss + s) * GHh + lane + 32];
    float gw0 = gate_W2[s * GHh + lane];
    float gw1 = gate_W2[s * GHh + lane + 32];
    float b2 = gate_b2[s];

    float h0[Bb], h1[Bb], ee[Bb];
#pragma unroll
    for (int b = 0; b < Bb; b++) {
        long row = (long)t * 32 + b * 4 + s;
        const float* hp = &g_hpart[row * GHh];
        h0[b] = hp[lane];
        h1[b] = hp[lane + 32];
        ee[b] = g_errsq[row];
    }

    float gsum = 0.f;
#pragma unroll
    for (int b = 0; b < Bb; b++) {
        long row = (long)t * 32 + b * 4 + s;
        float e = (t > 0) ? sqrtf(ee[b] + 1e-8f) : 0.f;
        float z = (e - mu) / sig;
        float v0 = h0[b] + z * w1z0 + sb0;
        float v1 = h1[b] + z * w1z1 + sb1;
        float a = fmaxf(v0, 0.f) * gw0 + fmaxf(v1, 0.f) * gw1;
#pragma unroll
        for (int o = 16; o > 0; o >>= 1) a += __shfl_xor_sync(0xffffffffu, a, o);
        if (lane == 0) {
            float g = 1.f / (1.f + expf(-(a + b2)));
            g_gall[(size_t)st * (Tt * Bb * Ss) + row] = g;
            gsum += g;
        }
    }
    if (lane == 0)
        g_gmean[st * Tt * Ss + t * Ss + s] = gsum * 0.125f;
}

// ============ fused gate tail: state machine (LDS) + ge gather (single CTA) ===========
__global__ void __launch_bounds__(1024, 1) gate_sm_kernel() {
    extern __shared__ float dyn[];
    float* sgm = dyn;
    int* sst = (int*)(dyn + 3 * Tt * Ss);
    const int tid = threadIdx.x;

    for (int i = tid; i < 3 * Tt * Ss; i += 1024) sgm[i] = g_gmean[i];
    __syncthreads();

    if (tid < Ss) {
        float ema = 0.5f; int st = 0;
#pragma unroll 4
        for (int t = 0; t < Tt; t++) {
            sst[t * 4 + tid] = st;
            float g0 = sgm[0 * Tt * Ss + t * 4 + tid];
            float g1 = sgm[1 * Tt * Ss + t * 4 + tid];
            float g2 = sgm[2 * Tt * Ss + t * 4 + tid];
            float gm = (st == 0) ? g0 : ((st == 1) ? g1 : g2);
            ema = 0.99f * ema + 0.01f * gm;
            int ns = st;
            if (st == 0) { if (ema < 0.1f) ns = 1; }
            else if (st == 1) { if (ema < 0.03f) ns = 2; else if (ema > 0.25f) ns = 0; }
            else { if (ema > 0.25f) ns = 0; }
            st = ns;
        }
    }
    __syncthreads();

    for (int i = tid; i < Tt * Bb * Ss; i += 1024) {
        int t = i >> 5, s = i & 3;
        int st = sst[t * 4 + s];
        float gain = (st == 0) ? 1.0f : ((st == 1) ? 0.5f : 0.1f);
        g_ge[i] = g_gall[(size_t)st * (Tt * Bb * Ss) + i] * gain;
    }
}

// ======== m-scan: cp.async smem ring over fp16 wenc (64 stages, 8-batches, 7 deep) =====
__global__ void __launch_bounds__(32, 1) mscan_kernel(const float* __restrict__ w0,
                                                      float* __restrict__ out) {
    __shared__ uint2 ring[64][32];
    __shared__ float sge[Tt];
    int bid = blockIdx.x;
    int chunk = bid & 3, s = (bid >> 2) & 3, b = bid >> 4;
    int lane = threadIdx.x;
    int d = chunk * 128 + lane * 4;
    float4 m = *(const float4*)&w0[s * Dd + d];
    const int goff = b * 4 + s;

    for (int i = lane; i < Tt; i += 32) sge[i] = g_ge[i * 32 + goff];

    const __half* wp = &g_wencH[((long)b * Ss + s) * Dd + d];
    float4* op = (float4*)&out[((long)b * Tt) * (Ss * Dd) + s * Dd + d];
    const long wstride = (long)Bb * Ss * Dd;
    const long ostride = Ss * Dd / 4;
    const uint32_t rbase = smem_u32(&ring[0][0]) + (uint32_t)(lane * 8);

    constexpr int NB = Tt / 8;
#pragma unroll 1
    for (int bt = 0; bt < 7; bt++) {
#pragma unroll
        for (int j = 0; j < 8; j++) {
            int t = bt * 8 + j;
            CP_ASYNC8(rbase + (uint32_t)((t & 63) * 256),
                      (const void*)(wp + (long)t * wstride));
        }
        CP_COMMIT();
    }
#pragma unroll 1
    for (int bt = 0; bt < NB; bt++) {
        if (bt + 7 < NB) {
#pragma unroll
            for (int j = 0; j < 8; j++) {
                int t = (bt + 7) * 8 + j;
                CP_ASYNC8(rbase + (uint32_t)((t & 63) * 256),
                          (const void*)(wp + (long)t * wstride));
            }
            CP_COMMIT();
            CP_WAIT(7);
        } else {
            CP_WAIT(0);
        }
#pragma unroll
        for (int j = 0; j < 8; j++) {
            int t = bt * 8 + j;
            float ge = sge[t];
            float om = 1.f - ge;
            uint2 hv = ring[t & 63][lane];
            float2 w01 = __half22float2(*(__half2*)&hv.x);
            float2 w23 = __half22float2(*(__half2*)&hv.y);
            m.x = om * m.x + ge * w01.x;
            m.y = om * m.y + ge * w01.y;
            m.z = om * m.z + ge * w23.x;
            m.w = om * m.w + ge * w23.y;
            op[t * ostride] = m;
        }
    }
}

// ---------------- launch (fork/join graph; tail overlaps wenc GEMM) ----------
static cudaStream_t make_stream(int priority) {
    cudaStream_t s;
    cudaStreamCreateWithPriority(&s, cudaStreamNonBlocking, priority);
    return s;
}
static cudaEvent_t make_event() {
    cudaEvent_t e;
    cudaEventCreateWithFlags(&e, cudaEventDisableTiming);
    return e;
}

extern "C" void kernel_launch(void* const* d_in, const int* in_sizes, int n_in,
                              void* d_out, int out_size) {
    const float* h_seq       = (const float*)d_in[0];
    const float* pred_W      = (const float*)d_in[1];
    const float* pred_b      = (const float*)d_in[2];
    const float* gate_W1     = (const float*)d_in[3];
    const float* gate_b1     = (const float*)d_in[4];
    const float* gate_W2     = (const float*)d_in[5];
    const float* gate_b2     = (const float*)d_in[6];
    const float* write_W     = (const float*)d_in[7];
    const float* write_b     = (const float*)d_in[8];
    const float* w0          = (const float*)d_in[9];
    const float* state_embed = (const float*)d_in[10];
    float* out = (float*)d_out;

    __half *p_wencH;
    float *p_hpart;
    cudaGetSymbolAddress((void**)&p_wencH, g_wencH);
    cudaGetSymbolAddress((void**)&p_hpart, g_hpart);
    __half *pAhi, *pAlo, *pPW, *pWW, *pGW;
    cudaGetSymbolAddress((void**)&pAhi, g_Ahi);
    cudaGetSymbolAddress((void**)&pAlo, g_Alo);
    cudaGetSymbolAddress((void**)&pPW,  g_PW);
    cudaGetSymbolAddress((void**)&pWW,  g_WW);
    cudaGetSymbolAddress((void**)&pGW,  g_GW);

    constexpr int SMEM_BIG  = 2 * (128 * 128 + 128 * 128);        //  65536
    constexpr int SMEM_GATEGEMM = 2 * (2 * 128 * 128 + 64 * 128); //  81920
    constexpr int SMEM_STATS = 3 * Tt * Ss * 4;                   //  98304
    constexpr int SMEM_GATE  = 4 * Tt * Ss * 4;                   // 131072
    cudaFuncSetAttribute((const void*)mma_gemm_big<true, false>, cudaFuncAttributeMaxDynamicSharedMemorySize, SMEM_BIG);
    cudaFuncSetAttribute((const void*)mma_gemm_big<false, true>, cudaFuncAttributeMaxDynamicSharedMemorySize, SMEM_BIG);
    cudaFuncSetAttribute((const void*)mma_gemm_gate, cudaFuncAttributeMaxDynamicSharedMemorySize, SMEM_GATEGEMM);
    cudaFuncSetAttribute((const void*)stats_kernel,   cudaFuncAttributeMaxDynamicSharedMemorySize, SMEM_STATS);
    cudaFuncSetAttribute((const void*)gate_sm_kernel, cudaFuncAttributeMaxDynamicSharedMemorySize, SMEM_GATE);

    static int loPri = 0, hiPri = 0;
    static const int priOk = [](){ return cudaDeviceGetStreamPriorityRange(&loPri, &hiPri); }();
    (void)priOk;
    static cudaStream_t sG = make_stream(hiPri);   // gate GEMM branch
    static cudaStream_t sT = make_stream(hiPri);   // tail branch (overlaps wenc GEMM)
    static cudaEvent_t evA = make_event();
    static cudaEvent_t evP = make_event();
    static cudaEvent_t evG = make_event();
    static cudaEvent_t evT = make_event();

    dim3 gBig(Dd / 128, (Bb * Tt) / 128, Ss);      // (4, 128, 4) = 2048 CTAs
    dim3 gGate(1, (Bb * Tt) / 128, Ss);

    // ---- main stream ----
    convert_h_kernel<<<(Bb * Tt * Dd) / 256, 256>>>(h_seq, pAhi, pAlo);
    cudaEventRecord(evA, 0);

    // ---- gate branch (high priority) ----
    transpose_gw_kernel<<<dim3(2, 16, 4), dim3(32, 8), 0, sG>>>(gate_W1, pGW);
    seb_kernel<<<3, 256, 0, sG>>>(gate_W1, state_embed);
    cudaStreamWaitEvent(sG, evA, 0);
    mma_gemm_gate<<<gGate, 512, SMEM_GATEGEMM, sG>>>(pAhi, pAlo, pGW, gate_b1, p_hpart);
    cudaEventRecord(evG, sG);

    // ---- main stream: both weight transposes, pred GEMM, then wenc GEMM ----
    transpose_both_kernel<<<dim3(16, 16, 8), dim3(32, 8)>>>(pred_W, write_W, pPW, pWW);
    mma_gemm_big<true, false><<<gBig, 512, SMEM_BIG>>>(pAhi, pPW, pred_b, nullptr, h_seq);
    cudaEventRecord(evP, 0);
    mma_gemm_big<false, true><<<gBig, 512, SMEM_BIG>>>(pAhi, pWW, write_b, p_wencH, nullptr);

    // ---- tail branch (high priority; overlaps the wenc GEMM) ----
    cudaStreamWaitEvent(sT, evP, 0);
    stats_kernel<<<1, 1024, SMEM_STATS, sT>>>();
    cudaStreamWaitEvent(sT, evG, 0);
    gall_kernel<<<Tt, 384, 0, sT>>>(gate_W1, gate_W2, gate_b2);
    gate_sm_kernel<<<1, 1024, SMEM_GATE, sT>>>();
    cudaEventRecord(evT, sT);

    // ---- main stream: mscan after wenc (in-order) and tail (event) ----
    cudaStreamWaitEvent(0, evT, 0);
    mscan_kernel<<<128, 32>>>(w0, out);
}

// round 14
// speedup vs baseline: 1.0648x; 1.0648x over previous
#include <cuda_runtime.h>
#include <cuda_fp16.h>
#include <cstdint>

// Problem constants (fixed shapes)
#define Tt 2048
#define Bb 8
#define Dd 512
#define Ss 4
#define GHh 64

// ---------------- scratch (static device globals; no runtime alloc) ----------------
__device__ __half g_wencH[(size_t)Bb*Tt*Ss*Dd]; // wenc stored fp16, layout [t][b][s][d]
__device__ float g_hpart[(size_t)Bb*Tt*Ss*GHh];  // layout [t][b][s][h]
__device__ float g_errsq[Tt*Bb*Ss];              // sum_d (pred_prev - h)^2, [t][b][s]
__device__ float g_mu   [Tt*Ss];
__device__ float g_sig  [Tt*Ss];
__device__ float g_gall [3*Tt*Bb*Ss];            // [st][t][b][s]
__device__ float g_gmean[3*Tt*Ss];
__device__ float g_ge   [Tt*Bb*Ss];
__device__ float g_seb  [3*Ss*GHh];

// fp16 operands: A (h_seq) hi/lo split; weights hi only
__device__ __half g_Ahi[(size_t)Bb*Tt*Dd];
__device__ __half g_Alo[(size_t)Bb*Tt*Dd];
__device__ __half g_PW [Ss*Dd*Dd];               // pred_W^T  [s][n][k]
__device__ __half g_WW [Ss*Dd*Dd];               // write_W^T
__device__ __half g_GW [Ss*GHh*Dd];              // gate_W1[0:512]^T

// ======================= portable PTX helpers (sm_80-level) =======================
__device__ __forceinline__ uint32_t smem_u32(const void* p) {
    uint32_t a;
    asm("{ .reg .u64 t; cvta.to.shared.u64 t, %1; cvt.u32.u64 %0, t; }" : "=r"(a) : "l"(p));
    return a;
}
#define CP_ASYNC16(dst, src) \
    asm volatile("cp.async.cg.shared.global [%0], [%1], 16;" :: "r"(dst), "l"(src))
#define CP_ASYNC8(dst, src) \
    asm volatile("cp.async.ca.shared.global [%0], [%1], 8;" :: "r"(dst), "l"(src))
#define CP_COMMIT() asm volatile("cp.async.commit_group;" ::: "memory")
#define CP_WAIT(n)  asm volatile("cp.async.wait_group %0;" :: "n"(n) : "memory")

__device__ __forceinline__ void ldsm_x4(uint32_t* r, uint32_t addr) {
    asm volatile("ldmatrix.sync.aligned.m8n8.x4.shared.b16 {%0,%1,%2,%3}, [%4];"
        : "=r"(r[0]), "=r"(r[1]), "=r"(r[2]), "=r"(r[3]) : "r"(addr));
}
__device__ __forceinline__ void mma16816(float* d, const uint32_t* a, const uint32_t* b) {
    asm volatile("mma.sync.aligned.m16n8k16.row.col.f32.f16.f16.f32 "
        "{%0,%1,%2,%3}, {%4,%5,%6,%7}, {%8,%9}, {%0,%1,%2,%3};"
        : "+f"(d[0]), "+f"(d[1]), "+f"(d[2]), "+f"(d[3])
        : "r"(a[0]), "r"(a[1]), "r"(a[2]), "r"(a[3]), "r"(b[0]), "r"(b[1]));
}
__device__ __forceinline__ uint32_t sw128(uint32_t bo) { return bo ^ ((bo >> 3) & 0x70); }

// ======================= conversion pre-passes =======================
__global__ void convert_h_kernel(const float* __restrict__ h,
                                 __half* __restrict__ hi,
                                 __half* __restrict__ lo) {
    size_t i = (size_t)blockIdx.x * 256 + threadIdx.x;
    float v = h[i];
    __half a = __float2half(v);
    hi[i] = a;
    lo[i] = __float2half(v - __half2float(a));
    if (blockIdx.x < (Tt * Bb * Ss) / 256)
        g_errsq[blockIdx.x * 256 + threadIdx.x] = 0.f;
}

__global__ void transpose_both_kernel(const float* __restrict__ predW,
                                      const float* __restrict__ writeW,
                                      __half* __restrict__ dPW,
                                      __half* __restrict__ dWW) {
    __shared__ float tile[32][33];
    int s = blockIdx.z & 3;
    int which = blockIdx.z >> 2;
    const float* src = (which == 0) ? predW : writeW;
    __half* dst = (which == 0) ? dPW : dWW;
    int n0 = blockIdx.x * 32, k0 = blockIdx.y * 32;
    const float* sp = src + (size_t)s * Dd * Dd;
    for (int i = threadIdx.y; i < 32; i += 8)
        tile[i][threadIdx.x] = sp[(size_t)(k0 + i) * Dd + n0 + threadIdx.x];
    __syncthreads();
    size_t dbase = (size_t)s * Dd * 512;
    for (int i = threadIdx.y; i < 32; i += 8) {
        float v = tile[threadIdx.x][i];
        size_t off = dbase + (size_t)(n0 + i) * 512 + k0 + threadIdx.x;
        dst[off] = __float2half(v);
    }
}

__global__ void transpose_gw_kernel(const float* __restrict__ src,
                                    __half* __restrict__ dhi) {
    __shared__ float tile[32][33];
    int s = blockIdx.z;
    int n0 = blockIdx.x * 32, k0 = blockIdx.y * 32;
    const float* sp = src + (size_t)s * 521 * GHh;
    for (int i = threadIdx.y; i < 32; i += 8)
        tile[i][threadIdx.x] = sp[(size_t)(k0 + i) * GHh + n0 + threadIdx.x];
    __syncthreads();
    size_t dbase = (size_t)s * GHh * 512;
    for (int i = threadIdx.y; i < 32; i += 8) {
        float v = tile[threadIdx.x][i];
        size_t off = dbase + (size_t)(n0 + i) * 512 + k0 + threadIdx.x;
        dhi[off] = __float2half(v);
    }
}

// ====== BIG GEMM: BM=256, BN=128, 1-pass fp16, 16 warps (4m x 4n, 64x32 tiles) =========
// 3-stage cp.async pipeline (stage 48 KB x3 = 144 KB)
__device__ __forceinline__ void load_chunk_big(int tid, uint32_t base,
    const __half* __restrict__ Ahi, const __half* __restrict__ Bhi, int k0) {
    constexpr int A_BYTES = 256 * 128;
#pragma unroll
    for (int it = 0; it < 6; it++) {               // 384 rows x 8 segs / 512 threads
        int idx = tid + it * 512;
        int seg = idx & 7, q = idx >> 3;
        const __half* src;
        uint32_t toff;
        int r;
        if (q < 256) { src = Ahi; toff = 0;       r = q; }
        else         { src = Bhi; toff = A_BYTES; r = q - 256; }
        uint32_t bo = r * 128 + seg * 16;
        uint32_t dst = base + toff + sw128(bo);
        const void* g = (const void*)(src + (size_t)r * 512 + k0 + seg * 8);
        CP_ASYNC16(dst, g);
    }
}

template<bool FUSE_ERR, bool OUT_HALF>
__global__ void __launch_bounds__(512, 1)
mma_gemm_big(const __half* __restrict__ Ahi, const __half* __restrict__ BhiBase,
             const float* __restrict__ biasBase, void* __restrict__ outBase,
             const float* __restrict__ hseq) {
    constexpr int NC = 8;
    constexpr int A_BYTES = 256 * 128;
    constexpr int B_BYTES = 128 * 128;
    constexpr int STAGE = A_BYTES + B_BYTES;       // 49152
    constexpr int NF = 4;                          // warp N = 32
    constexpr int MF = 4;                          // warp M = 64

    extern __shared__ char smem[];
    const uint32_t tiles = smem_u32(smem);

    const int s = blockIdx.z;
    const int nBlock = blockIdx.x * 128;
    const int mBlock = blockIdx.y * 256;
    const __half* Ahi_t = Ahi + (size_t)mBlock * 512;
    const __half* Bhi_t = BhiBase + ((size_t)s * 512 + nBlock) * 512;
    const float* bias = biasBase + s * 512 + nBlock;

    const int tid = threadIdx.x;
    const int lane = tid & 31, w = tid >> 5;
    const int wm = (w & 3) * 64;
    const int wn = (w >> 2) * 32;

    float acc[MF][NF][4];
#pragma unroll
    for (int mf = 0; mf < MF; mf++)
#pragma unroll
        for (int nf = 0; nf < NF; nf++)
#pragma unroll
            for (int i = 0; i < 4; i++) acc[mf][nf][i] = 0.f;

    const uint32_t aRow = (uint32_t)(wm + (lane & 15));
    const uint32_t aCol = (uint32_t)((lane >> 4) * 16);
    const uint32_t bRow = (uint32_t)(wn + ((lane >> 4) & 1) * 8 + (lane & 7));
    const uint32_t bCol = (uint32_t)(((lane >> 3) & 1) * 16);

    // prologue: chunks 0, 1 in flight
    load_chunk_big(tid, tiles,          Ahi_t, Bhi_t, 0);
    CP_COMMIT();
    load_chunk_big(tid, tiles + STAGE,  Ahi_t, Bhi_t, 64);
    CP_COMMIT();

    int buf = 0;
    for (int ck = 0; ck < NC; ck++) {
        if (ck + 2 < NC) {
            int nbuf = (buf + 2) % 3;
            load_chunk_big(tid, tiles + nbuf * STAGE, Ahi_t, Bhi_t, (ck + 2) * 64);
            CP_COMMIT();
            CP_WAIT(2);
        } else if (ck + 1 < NC) {
            CP_WAIT(1);
        } else {
            CP_WAIT(0);
        }
        __syncthreads();

        const uint32_t aH = tiles + buf * STAGE;
        const uint32_t bH = aH + A_BYTES;

#pragma unroll
        for (int k16 = 0; k16 < 4; k16++) {
            uint32_t fa[MF][4];
#pragma unroll
            for (int mf = 0; mf < MF; mf++) {
                uint32_t bo = (aRow + mf * 16) * 128 + (uint32_t)(k16 * 32) + aCol;
                ldsm_x4(fa[mf], aH + sw128(bo));
            }
            uint32_t fb[NF][2];
#pragma unroll
            for (int nf2 = 0; nf2 < NF / 2; nf2++) {
                uint32_t bo = (bRow + nf2 * 16) * 128 + (uint32_t)(k16 * 32) + bCol;
                uint32_t r[4];
                ldsm_x4(r, bH + sw128(bo));
                fb[2*nf2][0] = r[0]; fb[2*nf2][1] = r[1];
                fb[2*nf2+1][0] = r[2]; fb[2*nf2+1][1] = r[3];
            }
#pragma unroll
            for (int mf = 0; mf < MF; mf++)
#pragma unroll
                for (int nf = 0; nf < NF; nf++)
                    mma16816(acc[mf][nf], fa[mf], fb[nf]);
        }
        __syncthreads();
        buf = (buf + 1) % 3;
    }

#pragma unroll
    for (int mf = 0; mf < MF; mf++) {
#pragma unroll
        for (int rr = 0; rr < 2; rr++) {
            int m = mBlock + wm + mf * 16 + rr * 8 + (lane >> 2);  // m = b*T + t
            int t = m & (Tt - 1), b = m >> 11;
            if (FUSE_ERR) {
                float ssum = 0.f;
                if (t < Tt - 1) {
                    const float* hrow = hseq + ((size_t)(b * Tt + t + 1)) * Dd + nBlock;
#pragma unroll
                    for (int nf = 0; nf < NF; nf++) {
                        int col = wn + nf * 8 + (lane & 3) * 2;
                        float2 hv = *(const float2*)&hrow[col];
                        float dx = acc[mf][nf][2 * rr]     + bias[col]     - hv.x;
                        float dy = acc[mf][nf][2 * rr + 1] + bias[col + 1] - hv.y;
                        ssum += dx * dx + dy * dy;
                    }
                }
                ssum += __shfl_xor_sync(0xffffffffu, ssum, 1);
                ssum += __shfl_xor_sync(0xffffffffu, ssum, 2);
                if ((lane & 3) == 0 && t < Tt - 1)
                    atomicAdd(&g_errsq[(t + 1) * 32 + b * 4 + s], ssum);
            } else {
                size_t rowoff = ((size_t)(t * Bb + b) * Ss + s) * 512 + nBlock;
#pragma unroll
                for (int nf = 0; nf < NF; nf++) {
                    int col = wn + nf * 8 + (lane & 3) * 2;
                    float vx = acc[mf][nf][2 * rr]     + bias[col];
                    float vy = acc[mf][nf][2 * rr + 1] + bias[col + 1];
                    if (OUT_HALF) {
                        __half2 hv = __floats2half2_rn(vx, vy);
                        *(__half2*)((__half*)outBase + rowoff + col) = hv;
                    } else {
                        float2 v; v.x = vx; v.y = vy;
                        *(float2*)((float*)outBase + rowoff + col) = v;
                    }
                }
            }
        }
    }
}

// ============ gate GEMM: BM=128, BN=64, 2-pass, 16 warps, 2 CTAs/SM (round-13 win) =====
__device__ __forceinline__ void load_chunk_gate(int tid, uint32_t base,
    const __half* __restrict__ Ahi, const __half* __restrict__ Alo,
    const __half* __restrict__ Bhi, int k0) {
    constexpr int A_BYTES = 128 * 128;
#pragma unroll
    for (int it = 0; it < 5; it++) {
        int idx = tid + it * 512;
        int seg = idx & 7, q = idx >> 3;
        const __half* src;
        uint32_t toff;
        int r;
        if (q < 128)      { src = Ahi; toff = 0;            r = q; }
        else if (q < 256) { src = Alo; toff = A_BYTES;      r = q - 128; }
        else              { src = Bhi; toff = 2 * A_BYTES;  r = q - 256; }
        uint32_t bo = r * 128 + seg * 16;
        uint32_t dst = base + toff + sw128(bo);
        const void* g = (const void*)(src + (size_t)r * 512 + k0 + seg * 8);
        CP_ASYNC16(dst, g);
    }
}

__global__ void __launch_bounds__(512, 2)
mma_gemm_gate(const __half* __restrict__ Ahi, const __half* __restrict__ Alo,
              const __half* __restrict__ BhiBase,
              const float* __restrict__ biasBase, float* __restrict__ outBase) {
    constexpr int NC = 8;
    constexpr int A_BYTES = 128 * 128;
    constexpr int B_BYTES = 64 * 128;
    constexpr int STAGE = 2 * A_BYTES + B_BYTES;   // 40960
    constexpr int NF = 2;

    extern __shared__ char smem[];
    const uint32_t tiles = smem_u32(smem);

    const int s = blockIdx.z;
    const int mBlock = blockIdx.y * 128;
    const __half* Ahi_t = Ahi + (size_t)mBlock * 512;
    const __half* Alo_t = Alo + (size_t)mBlock * 512;
    const __half* Bhi_t = BhiBase + (size_t)s * GHh * 512;
    const float* bias = biasBase + s * GHh;

    const int tid = threadIdx.x;
    const int lane = tid & 31, w = tid >> 5;
    const int wm = (w & 3) * 32;
    const int wn = (w >> 2) * 16;

    float acc[2][NF][4];
#pragma unroll
    for (int mf = 0; mf < 2; mf++)
#pragma unroll
        for (int nf = 0; nf < NF; nf++)
#pragma unroll
            for (int i = 0; i < 4; i++) acc[mf][nf][i] = 0.f;

    const uint32_t aRow = (uint32_t)(wm + (lane & 15));
    const uint32_t aCol = (uint32_t)((lane >> 4) * 16);
    const uint32_t bRow = (uint32_t)(wn + ((lane >> 4) & 1) * 8 + (lane & 7));
    const uint32_t bCol = (uint32_t)(((lane >> 3) & 1) * 16);

    load_chunk_gate(tid, tiles, Ahi_t, Alo_t, Bhi_t, 0);
    CP_COMMIT();

    for (int ck = 0; ck < NC; ck++) {
        const int nx = ck + 1;
        if (nx < NC) {
            load_chunk_gate(tid, tiles + (nx & 1) * STAGE, Ahi_t, Alo_t, Bhi_t, nx * 64);
            CP_COMMIT();
            CP_WAIT(1);
        } else {
            CP_WAIT(0);
        }
        __syncthreads();

        const uint32_t aH = tiles + (ck & 1) * STAGE;
        const uint32_t aL = aH + A_BYTES;
        const uint32_t bH = aH + 2 * A_BYTES;

#pragma unroll
        for (int k16 = 0; k16 < 4; k16++) {
            uint32_t fa_h[2][4], fa_l[2][4];
#pragma unroll
            for (int mf = 0; mf < 2; mf++) {
                uint32_t bo = (aRow + mf * 16) * 128 + (uint32_t)(k16 * 32) + aCol;
                ldsm_x4(fa_h[mf], aH + sw128(bo));
                ldsm_x4(fa_l[mf], aL + sw128(bo));
            }
            uint32_t fb[NF][2];
            {
                uint32_t bo = bRow * 128 + (uint32_t)(k16 * 32) + bCol;
                uint32_t r[4];
                ldsm_x4(r, bH + sw128(bo));
                fb[0][0] = r[0]; fb[0][1] = r[1];
                fb[1][0] = r[2]; fb[1][1] = r[3];
            }
#pragma unroll
            for (int mf = 0; mf < 2; mf++)
#pragma unroll
                for (int nf = 0; nf < NF; nf++) {
                    mma16816(acc[mf][nf], fa_h[mf], fb[nf]);
                    mma16816(acc[mf][nf], fa_l[mf], fb[nf]);
                }
        }
        __syncthreads();
    }

#pragma unroll
    for (int mf = 0; mf < 2; mf++) {
#pragma unroll
        for (int rr = 0; rr < 2; rr++) {
            int m = mBlock + wm + mf * 16 + rr * 8 + (lane >> 2);
            int t = m & (Tt - 1), b = m >> 11;
            float* orow = outBase + ((size_t)(t * Bb + b) * Ss + s) * GHh;
#pragma unroll
            for (int nf = 0; nf < NF; nf++) {
                int col = wn + nf * 8 + (lane & 3) * 2;
                float2 v;
                v.x = acc[mf][nf][2 * rr]     + bias[col];
                v.y = acc[mf][nf][2 * rr + 1] + bias[col + 1];
                *(float2*)&orow[col] = v;
            }
        }
    }
}

// ---------------- seb: state_embed @ gate_W1[513:521] ----------------
__global__ void seb_kernel(const float* __restrict__ gate_W1,
                           const float* __restrict__ state_embed) {
    int i = blockIdx.x * blockDim.x + threadIdx.x;
    if (i >= 3 * Ss * GHh) return;
    int h = i % GHh;
    int s = (i / GHh) % Ss;
    int st = i / (GHh * Ss);
    float acc = 0.f;
#pragma unroll
    for (int e = 0; e < 8; e++)
        acc += state_embed[st * 8 + e] * gate_W1[((size_t)s * 521 + 513 + e) * GHh + h];
    g_seb[i] = acc;
}

// ============ fused stats: em (par) -> mu chain (LDS) -> dev (par) -> sigma chain ======
__global__ void __launch_bounds__(1024, 1) stats_kernel() {
    extern __shared__ float dyn[];
    float* sem = dyn;
    float* smu = dyn + Tt * Ss;
    float* sdv = dyn + 2 * Tt * Ss;
    const int tid = threadIdx.x;

    for (int t = tid; t < Tt; t += 1024) {
        float s0 = 0.f, s1 = 0.f, s2 = 0.f, s3 = 0.f;
        if (t > 0) {
            const float4* p = (const float4*)&g_errsq[t * 32];
#pragma unroll
            for (int b = 0; b < Bb; b++) {
                float4 v = p[b];
                s0 += sqrtf(v.x + 1e-8f);
                s1 += sqrtf(v.y + 1e-8f);
                s2 += sqrtf(v.z + 1e-8f);
                s3 += sqrtf(v.w + 1e-8f);
            }
        }
        sem[t * 4 + 0] = s0 * 0.125f;
        sem[t * 4 + 1] = s1 * 0.125f;
        sem[t * 4 + 2] = s2 * 0.125f;
        sem[t * 4 + 3] = s3 * 0.125f;
    }
    __syncthreads();

    if (tid < Ss) {
        float mu = 0.f;
#pragma unroll 8
        for (int t = 0; t < Tt; t++) {
            smu[t * 4 + tid] = mu;
            g_mu[t * 4 + tid] = mu;
            float e = sem[t * 4 + tid];
            if (t > 0) mu = 0.99f * mu + 0.01f * e;
        }
    }
    __syncthreads();

    for (int t = tid; t < Tt; t += 1024) {
        float m0 = smu[t * 4 + 0], m1 = smu[t * 4 + 1];
        float m2 = smu[t * 4 + 2], m3 = smu[t * 4 + 3];
        float s0 = 0.f, s1 = 0.f, s2 = 0.f, s3 = 0.f;
        if (t > 0) {
            const float4* p = (const float4*)&g_errsq[t * 32];
#pragma unroll
            for (int b = 0; b < Bb; b++) {
                float4 v = p[b];
                s0 += fabsf(sqrtf(v.x + 1e-8f) - m0);
                s1 += fabsf(sqrtf(v.y + 1e-8f) - m1);
                s2 += fabsf(sqrtf(v.z + 1e-8f) - m2);
                s3 += fabsf(sqrtf(v.w + 1e-8f) - m3);
            }
        }
        sdv[t * 4 + 0] = s0 * 0.125f;
        sdv[t * 4 + 1] = s1 * 0.125f;
        sdv[t * 4 + 2] = s2 * 0.125f;
        sdv[t * 4 + 3] = s3 * 0.125f;
    }
    __syncthreads();

    if (tid < Ss) {
        float sg = 1.f;
#pragma unroll 8
        for (int t = 0; t < Tt; t++) {
            g_sig[t * 4 + tid] = sg;
            float d = sdv[t * 4 + tid];
            if (t > 0) sg = 0.99f * sg + 0.01f * d;
        }
    }
}

// ====== gate MLP over all 3 states, fused with gmean (block per t, warps loop b) ======
__global__ void __launch_bounds__(384, 1)
gall_kernel(const float* __restrict__ gate_W1,
            const float* __restrict__ gate_W2,
            const float* __restrict__ gate_b2) {
    int t = blockIdx.x;
    int w = threadIdx.x >> 5, lane = threadIdx.x & 31;
    int st = w >> 2, s = w & 3;

    float mu = g_mu[t * Ss + s];
    float sig = fmaxf(g_sig[t * Ss + s], 1e-3f);
    float w1z0 = gate_W1[((size_t)s * 521 + 512) * GHh + lane];
    float w1z1 = gate_W1[((size_t)s * 521 + 512) * GHh + lane + 32];
    float sb0 = g_seb[(st * Ss + s) * GHh + lane];
    float sb1 = g_seb[(st * Ss + s) * GHh + lane + 32];
    float gw0 = gate_W2[s * GHh + lane];
    float gw1 = gate_W2[s * GHh + lane + 32];
    float b2 = gate_b2[s];

    float h0[Bb], h1[Bb], ee[Bb];
#pragma unroll
    for (int b = 0; b < Bb; b++) {
        long row = (long)t * 32 + b * 4 + s;
        const float* hp = &g_hpart[row * GHh];
        h0[b] = hp[lane];
        h1[b] = hp[lane + 32];
        ee[b] = g_errsq[row];
    }

    float gsum = 0.f;
#pragma unroll
    for (int b = 0; b < Bb; b++) {
        long row = (long)t * 32 + b * 4 + s;
        float e = (t > 0) ? sqrtf(ee[b] + 1e-8f) : 0.f;
        float z = (e - mu) / sig;
        float v0 = h0[b] + z * w1z0 + sb0;
        float v1 = h1[b] + z * w1z1 + sb1;
        float a = fmaxf(v0, 0.f) * gw0 + fmaxf(v1, 0.f) * gw1;
#pragma unroll
        for (int o = 16; o > 0; o >>= 1) a += __shfl_xor_sync(0xffffffffu, a, o);
        if (lane == 0) {
            float g = 1.f / (1.f + expf(-(a + b2)));
            g_gall[(size_t)st * (Tt * Bb * Ss) + row] = g;
            gsum += g;
        }
    }
    if (lane == 0)
        g_gmean[st * Tt * Ss + t * Ss + s] = gsum * 0.125f;
}

// ============ fused gate tail: state machine (LDS) + ge gather (single CTA) ===========
__global__ void __launch_bounds__(1024, 1) gate_sm_kernel() {
    extern __shared__ float dyn[];
    float* sgm = dyn;
    int* sst = (int*)(dyn + 3 * Tt * Ss);
    const int tid = threadIdx.x;

    for (int i = tid; i < 3 * Tt * Ss; i += 1024) sgm[i] = g_gmean[i];
    __syncthreads();

    if (tid < Ss) {
        float ema = 0.5f; int st = 0;
#pragma unroll 4
        for (int t = 0; t < Tt; t++) {
            sst[t * 4 + tid] = st;
            float g0 = sgm[0 * Tt * Ss + t * 4 + tid];
            float g1 = sgm[1 * Tt * Ss + t * 4 + tid];
            float g2 = sgm[2 * Tt * Ss + t * 4 + tid];
            float gm = (st == 0) ? g0 : ((st == 1) ? g1 : g2);
            ema = 0.99f * ema + 0.01f * gm;
            int ns = st;
            if (st == 0) { if (ema < 0.1f) ns = 1; }
            else if (st == 1) { if (ema < 0.03f) ns = 2; else if (ema > 0.25f) ns = 0; }
            else { if (ema > 0.25f) ns = 0; }
            st = ns;
        }
    }
    __syncthreads();

    for (int i = tid; i < Tt * Bb * Ss; i += 1024) {
        int t = i >> 5, s = i & 3;
        int st = sst[t * 4 + s];
        float gain = (st == 0) ? 1.0f : ((st == 1) ? 0.5f : 0.1f);
        g_ge[i] = g_gall[(size_t)st * (Tt * Bb * Ss) + i] * gain;
    }
}

// ======== m-scan: cp.async smem ring over fp16 wenc (64 stages, 8-batches, 7 deep) =====
__global__ void __launch_bounds__(32, 1) mscan_kernel(const float* __restrict__ w0,
                                                      float* __restrict__ out) {
    __shared__ uint2 ring[64][32];
    __shared__ float sge[Tt];
    int bid = blockIdx.x;
    int chunk = bid & 3, s = (bid >> 2) & 3, b = bid >> 4;
    int lane = threadIdx.x;
    int d = chunk * 128 + lane * 4;
    float4 m = *(const float4*)&w0[s * Dd + d];
    const int goff = b * 4 + s;

    for (int i = lane; i < Tt; i += 32) sge[i] = g_ge[i * 32 + goff];

    const __half* wp = &g_wencH[((long)b * Ss + s) * Dd + d];
    float4* op = (float4*)&out[((long)b * Tt) * (Ss * Dd) + s * Dd + d];
    const long wstride = (long)Bb * Ss * Dd;
    const long ostride = Ss * Dd / 4;
    const uint32_t rbase = smem_u32(&ring[0][0]) + (uint32_t)(lane * 8);

    constexpr int NB = Tt / 8;
#pragma unroll 1
    for (int bt = 0; bt < 7; bt++) {
#pragma unroll
        for (int j = 0; j < 8; j++) {
            int t = bt * 8 + j;
            CP_ASYNC8(rbase + (uint32_t)((t & 63) * 256),
                      (const void*)(wp + (long)t * wstride));
        }
        CP_COMMIT();
    }
#pragma unroll 1
    for (int bt = 0; bt < NB; bt++) {
        if (bt + 7 < NB) {
#pragma unroll
            for (int j = 0; j < 8; j++) {
                int t = (bt + 7) * 8 + j;
                CP_ASYNC8(rbase + (uint32_t)((t & 63) * 256),
                          (const void*)(wp + (long)t * wstride));
            }
            CP_COMMIT();
            CP_WAIT(7);
        } else {
            CP_WAIT(0);
        }
#pragma unroll
        for (int j = 0; j < 8; j++) {
            int t = bt * 8 + j;
            float ge = sge[t];
            float om = 1.f - ge;
            uint2 hv = ring[t & 63][lane];
            float2 w01 = __half22float2(*(__half2*)&hv.x);
            float2 w23 = __half22float2(*(__half2*)&hv.y);
            m.x = om * m.x + ge * w01.x;
            m.y = om * m.y + ge * w01.y;
            m.z = om * m.z + ge * w23.x;
            m.w = om * m.w + ge * w23.y;
            op[t * ostride] = m;
        }
    }
}

// ---------------- launch (fork/join graph; tail overlaps wenc GEMM) ----------
static cudaStream_t make_stream(int priority) {
    cudaStream_t s;
    cudaStreamCreateWithPriority(&s, cudaStreamNonBlocking, priority);
    return s;
}
static cudaEvent_t make_event() {
    cudaEvent_t e;
    cudaEventCreateWithFlags(&e, cudaEventDisableTiming);
    return e;
}

extern "C" void kernel_launch(void* const* d_in, const int* in_sizes, int n_in,
                              void* d_out, int out_size) {
    const float* h_seq       = (const float*)d_in[0];
    const float* pred_W      = (const float*)d_in[1];
    const float* pred_b      = (const float*)d_in[2];
    const float* gate_W1     = (const float*)d_in[3];
    const float* gate_b1     = (const float*)d_in[4];
    const float* gate_W2     = (const float*)d_in[5];
    const float* gate_b2     = (const float*)d_in[6];
    const float* write_W     = (const float*)d_in[7];
    const float* write_b     = (const float*)d_in[8];
    const float* w0          = (const float*)d_in[9];
    const float* state_embed = (const float*)d_in[10];
    float* out = (float*)d_out;

    __half *p_wencH;
    float *p_hpart;
    cudaGetSymbolAddress((void**)&p_wencH, g_wencH);
    cudaGetSymbolAddress((void**)&p_hpart, g_hpart);
    __half *pAhi, *pAlo, *pPW, *pWW, *pGW;
    cudaGetSymbolAddress((void**)&pAhi, g_Ahi);
    cudaGetSymbolAddress((void**)&pAlo, g_Alo);
    cudaGetSymbolAddress((void**)&pPW,  g_PW);
    cudaGetSymbolAddress((void**)&pWW,  g_WW);
    cudaGetSymbolAddress((void**)&pGW,  g_GW);

    constexpr int SMEM_BIG  = 3 * (256 * 128 + 128 * 128);        // 147456 (3-stage)
    constexpr int SMEM_GATEGEMM = 2 * (2 * 128 * 128 + 64 * 128); //  81920
    constexpr int SMEM_STATS = 3 * Tt * Ss * 4;                   //  98304
    constexpr int SMEM_GATE  = 4 * Tt * Ss * 4;                   // 131072
    cudaFuncSetAttribute((const void*)mma_gemm_big<true, false>, cudaFuncAttributeMaxDynamicSharedMemorySize, SMEM_BIG);
    cudaFuncSetAttribute((const void*)mma_gemm_big<false, true>, cudaFuncAttributeMaxDynamicSharedMemorySize, SMEM_BIG);
    cudaFuncSetAttribute((const void*)mma_gemm_gate, cudaFuncAttributeMaxDynamicSharedMemorySize, SMEM_GATEGEMM);
    cudaFuncSetAttribute((const void*)stats_kernel,   cudaFuncAttributeMaxDynamicSharedMemorySize, SMEM_STATS);
    cudaFuncSetAttribute((const void*)gate_sm_kernel, cudaFuncAttributeMaxDynamicSharedMemorySize, SMEM_GATE);

    static int loPri = 0, hiPri = 0;
    static const int priOk = [](){ return cudaDeviceGetStreamPriorityRange(&loPri, &hiPri); }();
    (void)priOk;
    static cudaStream_t sG = make_stream(hiPri);   // gate GEMM branch
    static cudaStream_t sT = make_stream(hiPri);   // tail branch (overlaps wenc GEMM)
    static cudaEvent_t evA = make_event();
    static cudaEvent_t evP = make_event();
    static cudaEvent_t evG = make_event();
    static cudaEvent_t evT = make_event();

    dim3 gBig(Dd / 128, (Bb * Tt) / 256, Ss);      // (4, 64, 4)
    dim3 gGate(1, (Bb * Tt) / 128, Ss);

    // ---- main stream ----
    convert_h_kernel<<<(Bb * Tt * Dd) / 256, 256>>>(h_seq, pAhi, pAlo);
    cudaEventRecord(evA, 0);

    // ---- gate branch (high priority) ----
    transpose_gw_kernel<<<dim3(2, 16, 4), dim3(32, 8), 0, sG>>>(gate_W1, pGW);
    seb_kernel<<<3, 256, 0, sG>>>(gate_W1, state_embed);
    cudaStreamWaitEvent(sG, evA, 0);
    mma_gemm_gate<<<gGate, 512, SMEM_GATEGEMM, sG>>>(pAhi, pAlo, pGW, gate_b1, p_hpart);
    cudaEventRecord(evG, sG);

    // ---- main stream: both weight transposes, pred GEMM, then wenc GEMM ----
    transpose_both_kernel<<<dim3(16, 16, 8), dim3(32, 8)>>>(pred_W, write_W, pPW, pWW);
    mma_gemm_big<true, false><<<gBig, 512, SMEM_BIG>>>(pAhi, pPW, pred_b, nullptr, h_seq);
    cudaEventRecord(evP, 0);
    mma_gemm_big<false, true><<<gBig, 512, SMEM_BIG>>>(pAhi, pWW, write_b, p_wencH, nullptr);

    // ---- tail branch (high priority; overlaps the wenc GEMM) ----
    cudaStreamWaitEvent(sT, evP, 0);
    stats_kernel<<<1, 1024, SMEM_STATS, sT>>>();
    cudaStreamWaitEvent(sT, evG, 0);
    gall_kernel<<<Tt, 384, 0, sT>>>(gate_W1, gate_W2, gate_b2);
    gate_sm_kernel<<<1, 1024, SMEM_GATE, sT>>>();
    cudaEventRecord(evT, sT);

    // ---- main stream: mscan after wenc (in-order) and tail (event) ----
    cudaStreamWaitEvent(0, evT, 0);
    mscan_kernel<<<128, 32>>>(w0, out);
}